// round 13
// baseline (speedup 1.0000x reference)
#include <cuda_runtime.h>

// 2-layer LSTM (H=128, T=102400, B=8) + mean-pool + 2 FCs.
// 3-stage persistent pipeline: 24 blocks = 3 roles x 8 batches, 1 block/SM.
//   role 0: layer-0 recurrence  (Whh0 @ h0 + x_t*Wih0 + b)  -> ringA (h1_t)
//   role 1: layer-1 input proj  (Wih1 @ h1_t + b)           -> ringB (xp1_t)
//   role 2: layer-1 recurrence  (Whh1 @ h2 + xp1_t) + Kahan pooling + FCs
// Rings live in L2-resident __device__ globals; progress counters are reset
// by an init kernel every launch, so each graph replay is deterministic.

#define T_STEPS 102400
#define SLOTS   1024        // ring depth (power of 2)
#define CHUNK   8           // steps per flag publish (T divisible by 8)

__device__ int g_c0[8];                      // layer0 steps produced
__device__ int g_c1[8];                      // projection steps produced
__device__ int g_c2[8];                      // layer1 steps consumed
__device__ float g_ringA[8][SLOTS][128];     // h1_t   (4 MB)
__device__ float g_ringB[8][SLOTS][512];     // xp1_t  (16 MB)

__global__ void lstm_init() {
    if (threadIdx.x < 8) {
        g_c0[threadIdx.x] = 0;
        g_c1[threadIdx.x] = 0;
        g_c2[threadIdx.x] = 0;
    }
}

__device__ __forceinline__ float sigf(float x) {
    return 1.0f / (1.0f + __expf(-x));
}

__device__ __forceinline__ int volp(const int* p) {
    return *(volatile const int*)p;
}

// 128-wide dot for gate row g: cols 0..63 weights in registers, cols 64..127
// weights in SMEM (k-major: ws[k*512+g] -> consecutive lanes, conflict-free).
// h vector read from SMEM via broadcast LDS.128.
__device__ __forceinline__ float dot128(const float* __restrict__ hs,
                                        const float* __restrict__ ws,
                                        const float* __restrict__ wreg,
                                        int g) {
    float a0 = 0.f, a1 = 0.f, a2 = 0.f, a3 = 0.f;
    const float4* h4 = (const float4*)hs;
#pragma unroll
    for (int j = 0; j < 16; j++) {
        float4 hv = h4[j];
        a0 = fmaf(wreg[4*j+0], hv.x, a0);
        a1 = fmaf(wreg[4*j+1], hv.y, a1);
        a2 = fmaf(wreg[4*j+2], hv.z, a2);
        a3 = fmaf(wreg[4*j+3], hv.w, a3);
    }
#pragma unroll
    for (int j = 0; j < 16; j++) {
        float4 hv = h4[16 + j];
        a0 = fmaf(ws[(4*j+0)*512 + g], hv.x, a0);
        a1 = fmaf(ws[(4*j+1)*512 + g], hv.y, a1);
        a2 = fmaf(ws[(4*j+2)*512 + g], hv.z, a2);
        a3 = fmaf(ws[(4*j+3)*512 + g], hv.w, a3);
    }
    return (a0 + a1) + (a2 + a3);
}

__global__ void __launch_bounds__(512, 1)
lstm_pipe(const float* __restrict__ x,
          const float* __restrict__ Wih0, const float* __restrict__ Whh0,
          const float* __restrict__ bih0, const float* __restrict__ bhh0,
          const float* __restrict__ Wih1, const float* __restrict__ Whh1,
          const float* __restrict__ bih1, const float* __restrict__ bhh1,
          const float* __restrict__ fcW1, const float* __restrict__ fcb1,
          const float* __restrict__ fcW2, const float* __restrict__ fcb2,
          float* __restrict__ out) {
    extern __shared__ float smem[];
    float* ws   = smem;            // 64*512 floats = 128 KB (weight cols 64..127)
    float* hs   = smem + 32768;    // 128 floats (h vector / pooled)
    float* gbuf = smem + 32896;    // 512 floats (gate exchange / fc hidden)

    const int g    = threadIdx.x;          // gate row 0..511
    const int role = blockIdx.x >> 3;      // 0,1,2
    const int b    = blockIdx.x & 7;       // batch

    // ---- load weights: 64 cols to registers, 64 cols to SMEM (k-major) ----
    const float* W = (role == 0) ? Whh0 : (role == 1) ? Wih1 : Whh1;
    float wreg[64];
#pragma unroll
    for (int j = 0; j < 64; j++) wreg[j] = W[g * 128 + j];
    for (int j = 0; j < 64; j++) ws[j * 512 + g] = W[g * 128 + 64 + j];

    float bsum = 0.f, wx = 0.f;
    if (role == 0)      { bsum = bih0[g] + bhh0[g]; wx = Wih0[g]; }
    else if (role == 1) { bsum = bih1[g] + bhh1[g]; }

    if (g < 128) hs[g] = 0.f;
    __syncthreads();

    if (role == 0) {
        // ---------------- layer-0 recurrence ----------------
        const float* xb = x + (size_t)b * T_STEPS;
        float c = 0.f;
        for (int t = 0; t < T_STEPS; t++) {
            float acc = fmaf(wx, xb[t], bsum) + dot128(hs, ws, wreg, g);
            gbuf[g] = acc;
            __syncthreads();
            if (g < 128) {
                float iv = sigf(gbuf[g]);
                float fv = sigf(gbuf[128 + g]);
                float gv = tanhf(gbuf[256 + g]);
                float ov = sigf(gbuf[384 + g]);
                c = fmaf(fv, c, iv * gv);
                float h = ov * tanhf(c);
                hs[g] = h;
                *(volatile float*)&g_ringA[b][t & (SLOTS - 1)][g] = h;
            }
            if ((t & (CHUNK - 1)) == CHUNK - 1) {
                __threadfence();            // data visible before flag
                __syncthreads();
                if (g == 0) {
                    *(volatile int*)&g_c0[b] = t + 1;
                    int lim = t + 1 + CHUNK - SLOTS;   // ringA backpressure
                    if (lim > 0) while (volp(&g_c1[b]) < lim) __nanosleep(60);
                }
                __syncthreads();
            } else {
                __syncthreads();            // hs visible for next step
            }
        }
    } else if (role == 1) {
        // ---------------- layer-1 input projection ----------------
        for (int t = 0; t < T_STEPS; t++) {
            if ((t & (CHUNK - 1)) == 0) {
                if (g == 0) {
                    while (volp(&g_c0[b]) < t + CHUNK) __nanosleep(60);
                    int lim = t + CHUNK - SLOTS;       // ringB backpressure
                    if (lim > 0) while (volp(&g_c2[b]) < lim) __nanosleep(60);
                }
                __syncthreads();
                __threadfence();
            }
            int slot = t & (SLOTS - 1);
            if (g < 128) hs[g] = *(volatile float*)&g_ringA[b][slot][g];
            __syncthreads();
            float acc = bsum + dot128(hs, ws, wreg, g);
            *(volatile float*)&g_ringB[b][slot][g] = acc;
            if ((t & (CHUNK - 1)) == CHUNK - 1) {
                __threadfence();
                __syncthreads();
                if (g == 0) *(volatile int*)&g_c1[b] = t + 1;
                __syncthreads();
            } else {
                __syncthreads();
            }
        }
    } else {
        // ---------------- layer-1 recurrence + pooling + FCs ----------------
        float c = 0.f, pooled = 0.f, comp = 0.f;
        for (int t = 0; t < T_STEPS; t++) {
            if ((t & (CHUNK - 1)) == 0) {
                if (g == 0) {
                    while (volp(&g_c1[b]) < t + CHUNK) __nanosleep(60);
                }
                __syncthreads();
                __threadfence();
            }
            int slot = t & (SLOTS - 1);
            float xp = *(volatile float*)&g_ringB[b][slot][g];
            float acc = xp + dot128(hs, ws, wreg, g);
            gbuf[g] = acc;
            __syncthreads();
            if (g < 128) {
                float iv = sigf(gbuf[g]);
                float fv = sigf(gbuf[128 + g]);
                float gv = tanhf(gbuf[256 + g]);
                float ov = sigf(gbuf[384 + g]);
                c = fmaf(fv, c, iv * gv);
                float h = ov * tanhf(c);
                hs[g] = h;
                // Kahan-compensated pooling sum over 102400 steps
                float y = h - comp;
                float s = pooled + y;
                comp = (s - pooled) - y;
                pooled = s;
            }
            __syncthreads();
            if ((t & (CHUNK - 1)) == CHUNK - 1 && g == 0)
                *(volatile int*)&g_c2[b] = t + 1;   // slots consumed
        }
        // mean pool -> fc1 (relu) -> fc2
        if (g < 128) hs[g] = pooled * (1.0f / (float)T_STEPS);
        __syncthreads();
        if (g < 64) {
            float a = fcb1[g];
#pragma unroll 4
            for (int j = 0; j < 128; j++) a = fmaf(fcW1[g * 128 + j], hs[j], a);
            gbuf[g] = fmaxf(a, 0.f);
        }
        __syncthreads();
        if (g < 11) {
            float a = fcb2[g];
#pragma unroll
            for (int m = 0; m < 64; m++) a = fmaf(fcW2[g * 64 + m], gbuf[m], a);
            out[b * 11 + g] = a;
        }
    }
}

extern "C" void kernel_launch(void* const* d_in, const int* in_sizes, int n_in,
                              void* d_out, int out_size) {
    (void)in_sizes; (void)n_in; (void)out_size;
    cudaFuncSetAttribute(lstm_pipe,
                         cudaFuncAttributeMaxDynamicSharedMemorySize, 133632);
    lstm_init<<<1, 32>>>();
    lstm_pipe<<<24, 512, 133632>>>(
        (const float*)d_in[0],                         // x
        (const float*)d_in[1],  (const float*)d_in[2], // Wih0, Whh0
        (const float*)d_in[3],  (const float*)d_in[4], // bih0, bhh0
        (const float*)d_in[5],  (const float*)d_in[6], // Wih1, Whh1
        (const float*)d_in[7],  (const float*)d_in[8], // bih1, bhh1
        (const float*)d_in[9],  (const float*)d_in[10],// fcW1, fcb1
        (const float*)d_in[11], (const float*)d_in[12],// fcW2, fcb2
        (float*)d_out);
}

// round 14
// speedup vs baseline: 1.0045x; 1.0045x over previous
#include <cuda_runtime.h>

// 2-layer LSTM (H=128, T=102400, B=8) + mean-pool + 2 FCs.
// 3-stage persistent pipeline: 24 blocks = 3 roles x 8 batches, 1 block/SM.
//   role 0: layer-0 recurrence  (Whh0 @ h0 + x_t*Wih0 + b)  -> ringA (h1_t)
//   role 1: layer-1 input proj  (Wih1 @ h1_t + b)           -> ringB (xp1_t)
//   role 2: layer-1 recurrence  (Whh1 @ h2 + xp1_t) + Kahan pooling + FCs
// Rings live in L2-resident __device__ globals; progress counters are reset
// by an init kernel every launch, so each graph replay is deterministic.
//
// Per-block matvec: thread g owns gate row g. 64 weight cols in registers,
// 64 cols in SMEM as per-thread-contiguous float4 (stride 17 float4 -> pad
// makes 8-lane LDS.128 phases conflict-free). Activations are applied by all
// 512 threads on their own gate before the exchange.

#define T_STEPS 102400
#define SLOTS   1024        // ring depth (power of 2)
#define CHUNK   8           // steps per flag publish (T divisible by 8)

#define WS_STRIDE 17        // float4 stride per thread (16 used + 1 pad)
#define WS_F4     (512 * WS_STRIDE)          // 8704 float4
#define HS_OFF    (WS_F4 * 4)                // float offset of hs
#define GB_OFF    (HS_OFF + 128)             // float offset of gbuf
#define SMEM_BYTES ((GB_OFF + 512) * 4)      // 141824 bytes

__device__ int g_c0[8];                      // layer0 steps produced
__device__ int g_c1[8];                      // projection steps produced
__device__ int g_c2[8];                      // layer1 steps consumed
__device__ float g_ringA[8][SLOTS][128];     // h1_t   (4 MB)
__device__ float g_ringB[8][SLOTS][512];     // xp1_t  (16 MB)

__global__ void lstm_init() {
    if (threadIdx.x < 8) {
        g_c0[threadIdx.x] = 0;
        g_c1[threadIdx.x] = 0;
        g_c2[threadIdx.x] = 0;
    }
}

__device__ __forceinline__ float sigf(float x) {
    // 1/(1+e^-x) via MUFU EX2 + fast division (~2^-21 rel err)
    return __fdividef(1.0f, 1.0f + __expf(-x));
}
__device__ __forceinline__ float tanhfast(float x) {
    // 1 - 2/(e^{2x}+1); saturates correctly at +-inf
    return 1.0f - __fdividef(2.0f, __expf(2.0f * x) + 1.0f);
}

__device__ __forceinline__ int volp(const int* p) {
    return *(volatile const int*)p;
}

// 128-wide dot for gate row g: cols 0..63 from registers, cols 64..127 from
// SMEM float4 (per-thread contiguous, padded stride). h via broadcast LDS.128.
__device__ __forceinline__ float dot128(const float4* __restrict__ h4,
                                        const float4* __restrict__ wv,
                                        const float* __restrict__ wreg) {
    float a0 = 0.f, a1 = 0.f, a2 = 0.f, a3 = 0.f;
#pragma unroll
    for (int j = 0; j < 16; j++) {
        float4 hv = h4[j];
        a0 = fmaf(wreg[4*j+0], hv.x, a0);
        a1 = fmaf(wreg[4*j+1], hv.y, a1);
        a2 = fmaf(wreg[4*j+2], hv.z, a2);
        a3 = fmaf(wreg[4*j+3], hv.w, a3);
    }
#pragma unroll
    for (int j = 0; j < 16; j++) {
        float4 w  = wv[j];
        float4 hv = h4[16 + j];
        a0 = fmaf(w.x, hv.x, a0);
        a1 = fmaf(w.y, hv.y, a1);
        a2 = fmaf(w.z, hv.z, a2);
        a3 = fmaf(w.w, hv.w, a3);
    }
    return (a0 + a1) + (a2 + a3);
}

__global__ void __launch_bounds__(512, 1)
lstm_pipe(const float* __restrict__ x,
          const float* __restrict__ Wih0, const float* __restrict__ Whh0,
          const float* __restrict__ bih0, const float* __restrict__ bhh0,
          const float* __restrict__ Wih1, const float* __restrict__ Whh1,
          const float* __restrict__ bih1, const float* __restrict__ bhh1,
          const float* __restrict__ fcW1, const float* __restrict__ fcb1,
          const float* __restrict__ fcW2, const float* __restrict__ fcb2,
          float* __restrict__ out) {
    extern __shared__ float smem[];
    float4* ws4 = (float4*)smem;          // weight cols 64..127, padded
    float*  hs   = smem + HS_OFF;         // 128 floats (h vector / pooled)
    float*  gbuf = smem + GB_OFF;         // 512 floats (activated gates)

    const int g    = threadIdx.x;          // gate row 0..511
    const int grp  = g >> 7;               // 0=i 1=f 2=g 3=o (warp-uniform)
    const int role = blockIdx.x >> 3;      // 0,1,2
    const int b    = blockIdx.x & 7;       // batch

    // ---- load weights: 64 cols to registers, 64 cols to SMEM float4 ----
    const float* W = (role == 0) ? Whh0 : (role == 1) ? Wih1 : Whh1;
    float wreg[64];
#pragma unroll
    for (int j = 0; j < 64; j++) wreg[j] = W[g * 128 + j];
    const float4* Wrow4 = (const float4*)(W + g * 128 + 64);
    float4* wv = ws4 + g * WS_STRIDE;
#pragma unroll
    for (int j = 0; j < 16; j++) wv[j] = Wrow4[j];

    float bsum = 0.f, wx = 0.f;
    if (role == 0)      { bsum = bih0[g] + bhh0[g]; wx = Wih0[g]; }
    else if (role == 1) { bsum = bih1[g] + bhh1[g]; }

    if (g < 128) hs[g] = 0.f;
    __syncthreads();

    const float4* h4 = (const float4*)hs;

    if (role == 0) {
        // ---------------- layer-0 recurrence ----------------
        const float* xb = x + (size_t)b * T_STEPS;
        float c = 0.f;
        for (int t = 0; t < T_STEPS; t++) {
            float acc = fmaf(wx, __ldg(xb + t), bsum) + dot128(h4, wv, wreg);
            gbuf[g] = (grp == 2) ? tanhfast(acc) : sigf(acc);
            __syncthreads();
            if (g < 128) {
                float iv = gbuf[g];
                float fv = gbuf[128 + g];
                float gv = gbuf[256 + g];
                float ov = gbuf[384 + g];
                c = fmaf(fv, c, iv * gv);
                float h = ov * tanhfast(c);
                hs[g] = h;
                *(volatile float*)&g_ringA[b][t & (SLOTS - 1)][g] = h;
            }
            if ((t & (CHUNK - 1)) == CHUNK - 1) {
                __threadfence();            // ring data visible before flag
                __syncthreads();
                if (g == 0) {
                    *(volatile int*)&g_c0[b] = t + 1;
                    int lim = t + 1 + CHUNK - SLOTS;   // ringA backpressure
                    if (lim > 0) while (volp(&g_c1[b]) < lim) __nanosleep(60);
                }
                __syncthreads();
            } else {
                __syncthreads();            // hs visible for next step
            }
        }
    } else if (role == 1) {
        // ---------------- layer-1 input projection ----------------
        for (int t = 0; t < T_STEPS; t++) {
            if ((t & (CHUNK - 1)) == 0) {
                if (g == 0) {
                    while (volp(&g_c0[b]) < t + CHUNK) __nanosleep(60);
                    int lim = t + CHUNK - SLOTS;       // ringB backpressure
                    if (lim > 0) while (volp(&g_c2[b]) < lim) __nanosleep(60);
                }
                __syncthreads();
                __threadfence();
            }
            int slot = t & (SLOTS - 1);
            if (g < 128) hs[g] = *(volatile float*)&g_ringA[b][slot][g];
            __syncthreads();
            float acc = bsum + dot128(h4, wv, wreg);
            *(volatile float*)&g_ringB[b][slot][g] = acc;
            if ((t & (CHUNK - 1)) == CHUNK - 1) {
                __threadfence();
                __syncthreads();
                if (g == 0) *(volatile int*)&g_c1[b] = t + 1;
                __syncthreads();
            } else {
                __syncthreads();
            }
        }
    } else {
        // ---------------- layer-1 recurrence + pooling + FCs ----------------
        float c = 0.f, pooled = 0.f, comp = 0.f;
        for (int t = 0; t < T_STEPS; t++) {
            if ((t & (CHUNK - 1)) == 0) {
                if (g == 0) {
                    while (volp(&g_c1[b]) < t + CHUNK) __nanosleep(60);
                }
                __syncthreads();
                __threadfence();
            }
            int slot = t & (SLOTS - 1);
            float xp = *(volatile float*)&g_ringB[b][slot][g];
            float acc = xp + dot128(h4, wv, wreg);
            gbuf[g] = (grp == 2) ? tanhfast(acc) : sigf(acc);
            __syncthreads();
            if (g < 128) {
                float iv = gbuf[g];
                float fv = gbuf[128 + g];
                float gv = gbuf[256 + g];
                float ov = gbuf[384 + g];
                c = fmaf(fv, c, iv * gv);
                float h = ov * tanhfast(c);
                hs[g] = h;
                // Kahan-compensated pooling sum over 102400 steps
                float y = h - comp;
                float s = pooled + y;
                comp = (s - pooled) - y;
                pooled = s;
            }
            __syncthreads();
            if ((t & (CHUNK - 1)) == CHUNK - 1 && g == 0)
                *(volatile int*)&g_c2[b] = t + 1;   // slots consumed
        }
        // mean pool -> fc1 (relu) -> fc2
        if (g < 128) hs[g] = pooled * (1.0f / (float)T_STEPS);
        __syncthreads();
        if (g < 64) {
            float a = fcb1[g];
#pragma unroll 4
            for (int j = 0; j < 128; j++) a = fmaf(fcW1[g * 128 + j], hs[j], a);
            gbuf[g] = fmaxf(a, 0.f);
        }
        __syncthreads();
        if (g < 11) {
            float a = fcb2[g];
#pragma unroll
            for (int m = 0; m < 64; m++) a = fmaf(fcW2[g * 64 + m], gbuf[m], a);
            out[b * 11 + g] = a;
        }
    }
}

extern "C" void kernel_launch(void* const* d_in, const int* in_sizes, int n_in,
                              void* d_out, int out_size) {
    (void)in_sizes; (void)n_in; (void)out_size;
    cudaFuncSetAttribute(lstm_pipe,
                         cudaFuncAttributeMaxDynamicSharedMemorySize, SMEM_BYTES);
    lstm_init<<<1, 32>>>();
    lstm_pipe<<<24, 512, SMEM_BYTES>>>(
        (const float*)d_in[0],                         // x
        (const float*)d_in[1],  (const float*)d_in[2], // Wih0, Whh0
        (const float*)d_in[3],  (const float*)d_in[4], // bih0, bhh0
        (const float*)d_in[5],  (const float*)d_in[6], // Wih1, Whh1
        (const float*)d_in[7],  (const float*)d_in[8], // bih1, bhh1
        (const float*)d_in[9],  (const float*)d_in[10],// fcW1, fcb1
        (const float*)d_in[11], (const float*)d_in[12],// fcW2, fcb2
        (float*)d_out);
}

// round 15
// speedup vs baseline: 1.0834x; 1.0786x over previous
#include <cuda_runtime.h>

// 2-layer LSTM (H=128, T=102400, B=8) + mean-pool + 2 FCs.
// 3-stage persistent pipeline: 24 blocks = 3 roles x 8 batches, 1 block/SM.
//   role 0: layer-0 recurrence  (Whh0 @ h0 + x_t*Wih0 + b)  -> ringA (h1_t)
//   role 1: layer-1 input proj  (Wih1 @ h1_t + b)           -> ringB (xp1_t)
//   role 2: layer-1 recurrence  (Whh1 @ h2 + xp1_t) + Kahan pooling + FCs
// Rings in L2-resident __device__ globals; progress counters reset by an init
// kernel every launch -> graph replays are deterministic.
//
// Matvec: thread g owns gate row g. Dot product uses PACKED fp32x2 FMAs
// (fma.rn.f32x2 -> FFMA2): 64 FFMA2 instead of 128 FFMA per thread.
// Weights: 80 columns in registers (40 packed u64), 48 columns in SMEM as
// per-thread-contiguous ulonglong2 with padded stride (conflict-free LDS.128).

#define T_STEPS 102400
#define SLOTS   1024        // ring depth (power of 2)
#define CHUNK   8           // steps per flag publish

#define NREGC   80          // weight cols in registers (40 u64)
#define NSMC    48          // weight cols in SMEM (12 ulonglong2 per thread)
#define WS_STRIDE 13        // ulonglong2 stride per thread (12 used + 1 pad)
#define WS_U2   (512 * WS_STRIDE)            // ulonglong2 count
#define HS_OFF  (WS_U2 * 4)                  // float offset of hs (16B units*4)
#define GB_OFF  (HS_OFF + 128)               // float offset of gbuf
#define SMEM_BYTES ((GB_OFF + 512) * 4)      // 109,056 bytes

__device__ int g_c0[8];                      // layer0 steps produced
__device__ int g_c1[8];                      // projection steps produced
__device__ int g_c2[8];                      // layer1 steps consumed
__device__ float g_ringA[8][SLOTS][128];     // h1_t   (4 MB)
__device__ float g_ringB[8][SLOTS][512];     // xp1_t  (16 MB)

__global__ void lstm_init() {
    if (threadIdx.x < 8) {
        g_c0[threadIdx.x] = 0;
        g_c1[threadIdx.x] = 0;
        g_c2[threadIdx.x] = 0;
    }
}

typedef unsigned long long u64t;

__device__ __forceinline__ void fma2(u64t& d, u64t a, u64t b) {
    asm("fma.rn.f32x2 %0, %1, %2, %0;" : "+l"(d) : "l"(a), "l"(b));
}
__device__ __forceinline__ float red2(u64t a) {
    float lo, hi;
    asm("mov.b64 {%0,%1}, %2;" : "=f"(lo), "=f"(hi) : "l"(a));
    return lo + hi;
}
__device__ __forceinline__ u64t packf2(float lo, float hi) {
    u64t r;
    asm("mov.b64 %0, {%1,%2};" : "=l"(r) : "f"(lo), "f"(hi));
    return r;
}

__device__ __forceinline__ float sigf(float x) {
    return __fdividef(1.0f, 1.0f + __expf(-x));
}
__device__ __forceinline__ float tanhfast(float x) {
    return 1.0f - __fdividef(2.0f, __expf(2.0f * x) + 1.0f);
}
__device__ __forceinline__ int volp(const int* p) {
    return *(volatile const int*)p;
}

// 128-wide dot for one gate row: cols 0..79 weights in registers (packed),
// cols 80..127 in SMEM (ulonglong2, padded stride). h via broadcast LDS.128.
__device__ __forceinline__ float dot128(const ulonglong2* __restrict__ h2,
                                        const ulonglong2* __restrict__ wv,
                                        const u64t* __restrict__ wpk) {
    u64t a0 = 0ull, a1 = 0ull, a2 = 0ull, a3 = 0ull;
#pragma unroll
    for (int j = 0; j < 20; j += 2) {
        ulonglong2 hva = h2[j];
        fma2(a0, wpk[2*j],     hva.x);
        fma2(a1, wpk[2*j + 1], hva.y);
        ulonglong2 hvb = h2[j + 1];
        fma2(a2, wpk[2*j + 2], hvb.x);
        fma2(a3, wpk[2*j + 3], hvb.y);
    }
#pragma unroll
    for (int j = 0; j < 12; j += 2) {
        ulonglong2 hva = h2[20 + j];
        ulonglong2 wa  = wv[j];
        fma2(a0, wa.x, hva.x);
        fma2(a1, wa.y, hva.y);
        ulonglong2 hvb = h2[21 + j];
        ulonglong2 wb  = wv[j + 1];
        fma2(a2, wb.x, hvb.x);
        fma2(a3, wb.y, hvb.y);
    }
    return (red2(a0) + red2(a1)) + (red2(a2) + red2(a3));
}

__global__ void __launch_bounds__(512, 1)
lstm_pipe(const float* __restrict__ x,
          const float* __restrict__ Wih0, const float* __restrict__ Whh0,
          const float* __restrict__ bih0, const float* __restrict__ bhh0,
          const float* __restrict__ Wih1, const float* __restrict__ Whh1,
          const float* __restrict__ bih1, const float* __restrict__ bhh1,
          const float* __restrict__ fcW1, const float* __restrict__ fcb1,
          const float* __restrict__ fcW2, const float* __restrict__ fcb2,
          float* __restrict__ out) {
    extern __shared__ float smem[];
    ulonglong2* wsv = (ulonglong2*)smem;   // SMEM weight cols 80..127, padded
    float* hs   = smem + HS_OFF;           // 128 floats (h vector / pooled)
    float* gbuf = smem + GB_OFF;           // 512 floats (activated gates)

    const int g    = threadIdx.x;          // gate row 0..511
    const int grp  = g >> 7;               // 0=i 1=f 2=g 3=o (warp-uniform)
    const int role = blockIdx.x >> 3;      // 0,1,2
    const int b    = blockIdx.x & 7;       // batch

    // ---- weights: 80 cols packed into registers, 48 cols into SMEM ----
    const float* W = (role == 0) ? Whh0 : (role == 1) ? Wih1 : Whh1;
    u64t wpk[40];
#pragma unroll
    for (int p = 0; p < 40; p++)
        wpk[p] = packf2(W[g * 128 + 2*p], W[g * 128 + 2*p + 1]);
    ulonglong2* wv = wsv + g * WS_STRIDE;
    const float4* Wtail = (const float4*)(W + g * 128 + NREGC);
#pragma unroll
    for (int j = 0; j < 12; j++) {
        float4 w = Wtail[j];
        ulonglong2 u;
        u.x = packf2(w.x, w.y);
        u.y = packf2(w.z, w.w);
        wv[j] = u;
    }

    float bsum = 0.f, wx = 0.f;
    if (role == 0)      { bsum = bih0[g] + bhh0[g]; wx = Wih0[g]; }
    else if (role == 1) { bsum = bih1[g] + bhh1[g]; }

    if (g < 128) hs[g] = 0.f;
    __syncthreads();

    const ulonglong2* h2 = (const ulonglong2*)hs;

    if (role == 0) {
        // ---------------- layer-0 recurrence ----------------
        const float* xb = x + (size_t)b * T_STEPS;
        float c = 0.f;
        for (int t = 0; t < T_STEPS; t++) {
            float acc = fmaf(wx, __ldg(xb + t), bsum) + dot128(h2, wv, wpk);
            gbuf[g] = (grp == 2) ? tanhfast(acc) : sigf(acc);
            __syncthreads();
            if (g < 128) {
                float iv = gbuf[g];
                float fv = gbuf[128 + g];
                float gv = gbuf[256 + g];
                float ov = gbuf[384 + g];
                c = fmaf(fv, c, iv * gv);
                float h = ov * tanhfast(c);
                hs[g] = h;
                *(volatile float*)&g_ringA[b][t & (SLOTS - 1)][g] = h;
            }
            if ((t & (CHUNK - 1)) == CHUNK - 1) {
                __threadfence();            // ring data visible before flag
                __syncthreads();
                if (g == 0) {
                    *(volatile int*)&g_c0[b] = t + 1;
                    int lim = t + 1 + CHUNK - SLOTS;   // ringA backpressure
                    if (lim > 0) while (volp(&g_c1[b]) < lim) __nanosleep(60);
                }
                __syncthreads();
            } else {
                __syncthreads();            // hs visible for next step
            }
        }
    } else if (role == 1) {
        // ---------------- layer-1 input projection ----------------
        for (int t = 0; t < T_STEPS; t++) {
            if ((t & (CHUNK - 1)) == 0) {
                if (g == 0) {
                    while (volp(&g_c0[b]) < t + CHUNK) __nanosleep(60);
                    int lim = t + CHUNK - SLOTS;       // ringB backpressure
                    if (lim > 0) while (volp(&g_c2[b]) < lim) __nanosleep(60);
                }
                __syncthreads();
                __threadfence();
            }
            int slot = t & (SLOTS - 1);
            if (g < 128) hs[g] = *(volatile float*)&g_ringA[b][slot][g];
            __syncthreads();
            float acc = bsum + dot128(h2, wv, wpk);
            *(volatile float*)&g_ringB[b][slot][g] = acc;
            if ((t & (CHUNK - 1)) == CHUNK - 1) {
                __threadfence();
                __syncthreads();
                if (g == 0) *(volatile int*)&g_c1[b] = t + 1;
                __syncthreads();
            } else {
                __syncthreads();
            }
        }
    } else {
        // ---------------- layer-1 recurrence + pooling + FCs ----------------
        float c = 0.f, pooled = 0.f, comp = 0.f;
        for (int t = 0; t < T_STEPS; t++) {
            if ((t & (CHUNK - 1)) == 0) {
                if (g == 0) {
                    while (volp(&g_c1[b]) < t + CHUNK) __nanosleep(60);
                }
                __syncthreads();
                __threadfence();
            }
            int slot = t & (SLOTS - 1);
            float xp = *(volatile float*)&g_ringB[b][slot][g];
            float acc = xp + dot128(h2, wv, wpk);
            gbuf[g] = (grp == 2) ? tanhfast(acc) : sigf(acc);
            __syncthreads();
            if (g < 128) {
                float iv = gbuf[g];
                float fv = gbuf[128 + g];
                float gv = gbuf[256 + g];
                float ov = gbuf[384 + g];
                c = fmaf(fv, c, iv * gv);
                float h = ov * tanhfast(c);
                hs[g] = h;
                // Kahan-compensated pooling sum over 102400 steps
                float y = h - comp;
                float s = pooled + y;
                comp = (s - pooled) - y;
                pooled = s;
            }
            __syncthreads();
            if ((t & (CHUNK - 1)) == CHUNK - 1 && g == 0)
                *(volatile int*)&g_c2[b] = t + 1;   // slots consumed
        }
        // mean pool -> fc1 (relu) -> fc2
        if (g < 128) hs[g] = pooled * (1.0f / (float)T_STEPS);
        __syncthreads();
        if (g < 64) {
            float a = fcb1[g];
#pragma unroll 4
            for (int j = 0; j < 128; j++) a = fmaf(fcW1[g * 128 + j], hs[j], a);
            gbuf[g] = fmaxf(a, 0.f);
        }
        __syncthreads();
        if (g < 11) {
            float a = fcb2[g];
#pragma unroll
            for (int m = 0; m < 64; m++) a = fmaf(fcW2[g * 64 + m], gbuf[m], a);
            out[b * 11 + g] = a;
        }
    }
}

extern "C" void kernel_launch(void* const* d_in, const int* in_sizes, int n_in,
                              void* d_out, int out_size) {
    (void)in_sizes; (void)n_in; (void)out_size;
    cudaFuncSetAttribute(lstm_pipe,
                         cudaFuncAttributeMaxDynamicSharedMemorySize, SMEM_BYTES);
    lstm_init<<<1, 32>>>();
    lstm_pipe<<<24, 512, SMEM_BYTES>>>(
        (const float*)d_in[0],                         // x
        (const float*)d_in[1],  (const float*)d_in[2], // Wih0, Whh0
        (const float*)d_in[3],  (const float*)d_in[4], // bih0, bhh0
        (const float*)d_in[5],  (const float*)d_in[6], // Wih1, Whh1
        (const float*)d_in[7],  (const float*)d_in[8], // bih1, bhh1
        (const float*)d_in[9],  (const float*)d_in[10],// fcW1, fcb1
        (const float*)d_in[11], (const float*)d_in[12],// fcW2, fcb2
        (float*)d_out);
}

// round 16
// speedup vs baseline: 1.6268x; 1.5016x over previous
#include <cuda_runtime.h>
#include <cstdint>

// 2-layer LSTM (H=128, T=102400, B=8) + mean-pool + 2 FCs.
// 3-stage pipeline x 8 batches, each stage-batch = a 2-CTA CLUSTER (48 blocks).
// Each CTA owns 256 gate rows; each thread owns a 64-col half-row with ALL
// weights in registers (32 packed fp32x2 = 64 regs) -> zero SMEM weight loads.
// Gate exchange between cluster peers: one cp.async.bulk.shared::cluster (1KB)
// per step, completing on the peer's mbarrier (expect_tx, parity = t&1).
// Both CTAs redundantly compute c,h (identical fp32 ops -> identical values).
// Stages talk through L2-resident rings with chunked flags (reset per launch).

#define T_STEPS 102400
#define SLOTS   1024
#define CHUNK   8

__device__ int g_c0[8];        // role0 steps produced (rank0 writes)
__device__ int g_c1[8][2];     // role1 steps produced, per rank
__device__ int g_c2[8][2];     // role2 steps consumed, per rank
__device__ float g_ringA[8][SLOTS][128];   // h1_t
__device__ float g_ringB[8][SLOTS][512];   // xp1_t

__global__ void lstm_init() {
    int i = threadIdx.x;
    if (i < 8) {
        g_c0[i] = 0;
        g_c1[i][0] = 0; g_c1[i][1] = 0;
        g_c2[i][0] = 0; g_c2[i][1] = 0;
    }
}

typedef unsigned long long u64t;

__device__ __forceinline__ void fma2(u64t& d, u64t a, u64t b) {
    asm("fma.rn.f32x2 %0, %1, %2, %0;" : "+l"(d) : "l"(a), "l"(b));
}
__device__ __forceinline__ float red2(u64t a) {
    float lo, hi;
    asm("mov.b64 {%0,%1}, %2;" : "=f"(lo), "=f"(hi) : "l"(a));
    return lo + hi;
}
__device__ __forceinline__ u64t packf2(float lo, float hi) {
    u64t r;
    asm("mov.b64 %0, {%1,%2};" : "=l"(r) : "f"(lo), "f"(hi));
    return r;
}
__device__ __forceinline__ float sigf(float x) {
    return __fdividef(1.0f, 1.0f + __expf(-x));
}
__device__ __forceinline__ float tanhfast(float x) {
    return 1.0f - __fdividef(2.0f, __expf(2.0f * x) + 1.0f);
}
__device__ __forceinline__ int volp(const int* p) {
    return *(volatile const int*)p;
}
__device__ __forceinline__ uint32_t s2u(const void* p) {
    uint32_t a;
    asm("{ .reg .u64 t; cvta.to.shared.u64 t, %1; cvt.u32.u64 %0, t; }"
        : "=r"(a) : "l"(p));
    return a;
}
__device__ __forceinline__ uint32_t mapa_u(uint32_t la, uint32_t rank) {
    uint32_t ra;
    asm("mapa.shared::cluster.u32 %0, %1, %2;" : "=r"(ra) : "r"(la), "r"(rank));
    return ra;
}
__device__ __forceinline__ void mbar_wait_cl(uint32_t addr, uint32_t ph) {
    uint32_t done;
    asm volatile(
        "{ .reg .pred p;\n\t"
        "mbarrier.try_wait.parity.acquire.cluster.shared::cta.b64 p, [%1], %2;\n\t"
        "selp.b32 %0, 1, 0, p; }"
        : "=r"(done) : "r"(addr), "r"(ph) : "memory");
    while (!done) {
        asm volatile(
            "{ .reg .pred p;\n\t"
            "mbarrier.try_wait.parity.acquire.cluster.shared::cta.b64 p, [%1], %2, 0x989680;\n\t"
            "selp.b32 %0, 1, 0, p; }"
            : "=r"(done) : "r"(addr), "r"(ph) : "memory");
    }
}

// 64-wide half-row dot: all weights in registers, h segment via broadcast LDS.128
__device__ __forceinline__ float dot64(const ulonglong2* __restrict__ h2,
                                       const u64t* __restrict__ wpk) {
    u64t a0 = 0ull, a1 = 0ull, a2 = 0ull, a3 = 0ull;
#pragma unroll
    for (int j = 0; j < 16; j += 2) {
        ulonglong2 ha = h2[j];
        fma2(a0, wpk[2*j],     ha.x);
        fma2(a1, wpk[2*j + 1], ha.y);
        ulonglong2 hb = h2[j + 1];
        fma2(a2, wpk[2*j + 2], hb.x);
        fma2(a3, wpk[2*j + 3], hb.y);
    }
    return (red2(a0) + red2(a1)) + (red2(a2) + red2(a3));
}

__global__ void __launch_bounds__(512, 1) __cluster_dims__(2, 1, 1)
lstm_pipe(const float* __restrict__ x,
          const float* __restrict__ Wih0, const float* __restrict__ Whh0,
          const float* __restrict__ bih0, const float* __restrict__ bhh0,
          const float* __restrict__ Wih1, const float* __restrict__ Whh1,
          const float* __restrict__ bih1, const float* __restrict__ bhh1,
          const float* __restrict__ fcW1, const float* __restrict__ fcb1,
          const float* __restrict__ fcW2, const float* __restrict__ fcb2,
          float* __restrict__ out) {
    __shared__ __align__(16) float part[256];     // hi-half partial sums
    __shared__ __align__(16) float gbuf[2][512];  // activated gates, x2 parity
    __shared__ __align__(16) float hs[128];       // h vector
    __shared__ __align__(16) u64t  mbar[2];

    const int tid = threadIdx.x;
    uint32_t crank;
    asm("mov.u32 %0, %%cluster_ctarank;" : "=r"(crank));
    const int pair = blockIdx.x >> 1;
    const int role = pair >> 3;
    const int b    = pair & 7;
    const int half = tid >> 8;                 // 0 = cols 0-63, 1 = cols 64-127
    const int r    = tid & 255;                // row within CTA
    const int grow = (int)crank * 256 + r;     // global gate row 0..511
    const int isG  = ((grow >> 7) == 2);       // tanh gate?

    // ---- weights: the 64-col half-row, fully in registers ----
    const float* W = (role == 0) ? Whh0 : (role == 1) ? Wih1 : Whh1;
    const float* wr = W + grow * 128 + half * 64;
    u64t wpk[32];
#pragma unroll
    for (int p = 0; p < 32; p++) wpk[p] = packf2(wr[2*p], wr[2*p + 1]);

    float bsum = 0.f, wx = 0.f;
    if (half == 0) {
        if (role == 0)      { bsum = bih0[grow] + bhh0[grow]; wx = Wih0[grow]; }
        else if (role == 1) { bsum = bih1[grow] + bhh1[grow]; }
    }

    if (tid < 128) hs[tid] = 0.f;
    uint32_t l_mbar = s2u(&mbar[0]);
    if (tid == 0)
        asm volatile("mbarrier.init.shared.b64 [%0], %1;"
                     :: "r"(l_mbar), "r"(1u) : "memory");
    __syncthreads();
    asm volatile("barrier.cluster.arrive.aligned;" ::: "memory");
    asm volatile("barrier.cluster.wait.aligned;" ::: "memory");

    const uint32_t peer = crank ^ 1u;
    const uint32_t src0 = s2u(&gbuf[0][crank * 256]);
    const uint32_t src1 = s2u(&gbuf[1][crank * 256]);
    const uint32_t dst0 = mapa_u(src0, peer);
    const uint32_t dst1 = mapa_u(src1, peer);
    const uint32_t rmb  = mapa_u(l_mbar, peer);

    const ulonglong2* h2 = (const ulonglong2*)(hs + half * 64);

    if (role == 0) {
        // ---------------- layer-0 recurrence ----------------
        const float* xb = x + (size_t)b * T_STEPS;
        float c = 0.f;
        for (int t = 0; t < T_STEPS; t++) {
            const int par = t & 1;
            float acc = dot64(h2, wpk);
            if (half) part[r] = acc;
            __syncthreads();
            if (!half) {
                float tot = acc + part[r] + fmaf(wx, __ldg(xb + t), bsum);
                gbuf[par][grow] = isG ? tanhfast(tot) : sigf(tot);
            }
            __syncthreads();
            if (tid == 0) {
                asm volatile("fence.proxy.async.shared::cta;" ::: "memory");
                asm volatile(
                    "cp.async.bulk.shared::cluster.shared::cta.mbarrier::complete_tx::bytes [%0], [%1], %2, [%3];"
                    :: "r"(par ? dst1 : dst0), "r"(par ? src1 : src0),
                       "r"(1024u), "r"(rmb) : "memory");
                asm volatile("mbarrier.arrive.expect_tx.shared.b64 _, [%0], %1;"
                             :: "r"(l_mbar), "r"(1024u) : "memory");
            }
            mbar_wait_cl(l_mbar, (uint32_t)par);
            if (tid < 128) {
                float iv = gbuf[par][tid];
                float fv = gbuf[par][128 + tid];
                float gv = gbuf[par][256 + tid];
                float ov = gbuf[par][384 + tid];
                c = fmaf(fv, c, iv * gv);
                float h = ov * tanhfast(c);
                hs[tid] = h;
                if (crank == 0)
                    *(volatile float*)&g_ringA[b][t & (SLOTS - 1)][tid] = h;
            }
            if ((t & (CHUNK - 1)) == CHUNK - 1) {
                __threadfence();
                __syncthreads();
                if (crank == 0 && tid == 0) {
                    *(volatile int*)&g_c0[b] = t + 1;
                    int lim = t + 1 + CHUNK - SLOTS;     // ringA backpressure
                    if (lim > 0) {
                        while (volp(&g_c1[b][0]) < lim) __nanosleep(60);
                        while (volp(&g_c1[b][1]) < lim) __nanosleep(60);
                    }
                }
                __syncthreads();
            } else {
                __syncthreads();
            }
        }
    } else if (role == 1) {
        // ---------------- layer-1 input projection (no exchange) ----------------
        for (int t = 0; t < T_STEPS; t++) {
            if ((t & (CHUNK - 1)) == 0) {
                if (tid == 0) {
                    while (volp(&g_c0[b]) < t + CHUNK) __nanosleep(60);
                    int lim = t + CHUNK - SLOTS;         // ringB backpressure
                    if (lim > 0)
                        while (volp(&g_c2[b][crank]) < lim) __nanosleep(60);
                }
                __syncthreads();
                __threadfence();
            }
            const int slot = t & (SLOTS - 1);
            if (tid < 128)
                hs[tid] = *(volatile float*)&g_ringA[b][slot][tid];
            __syncthreads();
            float acc = dot64(h2, wpk);
            if (half) part[r] = acc;
            __syncthreads();
            if (!half)
                *(volatile float*)&g_ringB[b][slot][grow] = acc + part[r] + bsum;
            if ((t & (CHUNK - 1)) == CHUNK - 1) {
                __threadfence();
                __syncthreads();
                if (tid == 0) *(volatile int*)&g_c1[b][crank] = t + 1;
                __syncthreads();
            }
        }
    } else {
        // ---------------- layer-1 recurrence + pooling + FCs ----------------
        float c = 0.f, pooled = 0.f, comp = 0.f;
        for (int t = 0; t < T_STEPS; t++) {
            if ((t & (CHUNK - 1)) == 0) {
                if (tid == 0)
                    while (volp(&g_c1[b][crank]) < t + CHUNK) __nanosleep(60);
                __syncthreads();
                __threadfence();
            }
            const int par  = t & 1;
            const int slot = t & (SLOTS - 1);
            float xp = 0.f;
            if (!half)      // issue early; L2 latency hides under the dot
                xp = *(volatile float*)&g_ringB[b][slot][grow];
            float acc = dot64(h2, wpk);
            if (half) part[r] = acc;
            __syncthreads();
            if (!half) {
                float tot = acc + part[r] + xp;
                gbuf[par][grow] = isG ? tanhfast(tot) : sigf(tot);
            }
            __syncthreads();
            if (tid == 0) {
                asm volatile("fence.proxy.async.shared::cta;" ::: "memory");
                asm volatile(
                    "cp.async.bulk.shared::cluster.shared::cta.mbarrier::complete_tx::bytes [%0], [%1], %2, [%3];"
                    :: "r"(par ? dst1 : dst0), "r"(par ? src1 : src0),
                       "r"(1024u), "r"(rmb) : "memory");
                asm volatile("mbarrier.arrive.expect_tx.shared.b64 _, [%0], %1;"
                             :: "r"(l_mbar), "r"(1024u) : "memory");
            }
            mbar_wait_cl(l_mbar, (uint32_t)par);
            if (tid < 128) {
                float iv = gbuf[par][tid];
                float fv = gbuf[par][128 + tid];
                float gv = gbuf[par][256 + tid];
                float ov = gbuf[par][384 + tid];
                c = fmaf(fv, c, iv * gv);
                float h = ov * tanhfast(c);
                hs[tid] = h;
                if (crank == 0) {               // Kahan pooling on rank 0
                    float y = h - comp;
                    float s = pooled + y;
                    comp = (s - pooled) - y;
                    pooled = s;
                }
            }
            if ((t & (CHUNK - 1)) == CHUNK - 1) {
                __syncthreads();
                if (tid == 0) *(volatile int*)&g_c2[b][crank] = t + 1;
                __syncthreads();
            } else {
                __syncthreads();
            }
        }
        if (crank == 0) {
            if (tid < 128) hs[tid] = pooled * (1.0f / (float)T_STEPS);
            __syncthreads();
            if (tid < 64) {
                float a = fcb1[tid];
#pragma unroll 4
                for (int j = 0; j < 128; j++)
                    a = fmaf(fcW1[tid * 128 + j], hs[j], a);
                part[tid] = fmaxf(a, 0.f);
            }
            __syncthreads();
            if (tid < 11) {
                float a = fcb2[tid];
#pragma unroll
                for (int m = 0; m < 64; m++)
                    a = fmaf(fcW2[tid * 64 + m], part[m], a);
                out[b * 11 + tid] = a;
            }
        }
    }
}

extern "C" void kernel_launch(void* const* d_in, const int* in_sizes, int n_in,
                              void* d_out, int out_size) {
    (void)in_sizes; (void)n_in; (void)out_size;
    lstm_init<<<1, 32>>>();
    lstm_pipe<<<48, 512>>>(
        (const float*)d_in[0],
        (const float*)d_in[1],  (const float*)d_in[2],
        (const float*)d_in[3],  (const float*)d_in[4],
        (const float*)d_in[5],  (const float*)d_in[6],
        (const float*)d_in[7],  (const float*)d_in[8],
        (const float*)d_in[9],  (const float*)d_in[10],
        (const float*)d_in[11], (const float*)d_in[12],
        (float*)d_out);
}